// round 4
// baseline (speedup 1.0000x reference)
#include <cuda_runtime.h>
#include <math.h>

#define BQ   8
#define TQ   4096
#define NH   8
#define ES   64
#define EMBD 512
#define MF   32
#define BT   (BQ*TQ)      /* 32768 tokens */
#define HID  2048
#define LN_EPS 1e-5f
#define RSQRT_MF 0.17677669529663687f  /* 1/sqrt(32) */

// ---------------- scratch (device globals: alloc-free) ----------------
__device__ float g_qp[(size_t)BT*NH*MF];     // [tok][h][m]
__device__ float g_kp[(size_t)BT*NH*MF];
__device__ float g_v [(size_t)BT*EMBD];      // [tok][h*64+e]
__device__ float g_y [(size_t)BT*EMBD];
__device__ float g_x1[(size_t)BT*EMBD];      // x + attn
__device__ float g_h2[(size_t)BT*EMBD];      // LN2(x1)
__device__ float g_hid[(size_t)BT*HID];
__device__ float g_kptv[BQ*NH*MF*ES];        // [b][h][m][e]
__device__ float g_ks[BQ*NH*MF];             // [b][h][m]

// ---------------- K1: LN1 + kqv + random features ----------------
#define K1_TOK 32
__global__ __launch_bounds__(256) void k1_ln_kqv_feat(
    const float* __restrict__ x, const float* __restrict__ w,
    const float* __restrict__ kqv_w, const float* __restrict__ kqv_b,
    const float* __restrict__ g1, const float* __restrict__ b1)
{
    __shared__ float hs[EMBD];
    __shared__ float kqv_s[NH*192];
    __shared__ float ws[ES*MF];      // ws[e*MF+m], transposed w
    __shared__ float xd_s[16];
    __shared__ float red_s[16];
    __shared__ float mu_s, rstd_s;

    int tid = threadIdx.x;

    // load w transposed (w is [MF][ES] row-major)
    for (int i = tid; i < ES*MF; i += 256) {
        int m = i / ES, e = i % ES;
        ws[e*MF + m] = w[i];
    }
    // register-cache one kqv_w row per thread (threads 0..191)
    float wrow[ES];
    float bf = 0.f;
    if (tid < 192) {
        bf = kqv_b[tid];
        #pragma unroll
        for (int e = 0; e < ES; e++) wrow[e] = kqv_w[tid*ES + e];
    }
    __syncthreads();

    for (int it = 0; it < K1_TOK; it++) {
        size_t tok = (size_t)blockIdx.x * K1_TOK + it;
        const float* xr = x + tok * EMBD;

        // ---- LayerNorm 1 ----
        float v0 = xr[tid], v1 = xr[tid + 256];
        float s = v0 + v1, ss = v0*v0 + v1*v1;
        #pragma unroll
        for (int o = 16; o; o >>= 1) {
            s  += __shfl_xor_sync(0xffffffffu, s,  o);
            ss += __shfl_xor_sync(0xffffffffu, ss, o);
        }
        if ((tid & 31) == 0) { red_s[tid>>5] = s; red_s[8 + (tid>>5)] = ss; }
        __syncthreads();
        if (tid == 0) {
            float ts = 0, tss = 0;
            for (int i = 0; i < 8; i++) { ts += red_s[i]; tss += red_s[8+i]; }
            float mu = ts / EMBD;
            mu_s = mu;
            rstd_s = rsqrtf(tss/EMBD - mu*mu + LN_EPS);
        }
        __syncthreads();
        float mu = mu_s, rstd = rstd_s;
        hs[tid]       = (v0 - mu) * rstd * g1[tid]       + b1[tid];
        hs[tid + 256] = (v1 - mu) * rstd * g1[tid + 256] + b1[tid + 256];
        __syncthreads();

        // ---- kqv: out[h][f] = sum_e hs[h*64+e] * kqv_w[f][e] + b[f] ----
        if (tid < 192) {
            float acc[NH];
            #pragma unroll
            for (int h = 0; h < NH; h++) acc[h] = bf;
            #pragma unroll
            for (int e = 0; e < ES; e++) {
                float we = wrow[e];
                #pragma unroll
                for (int h = 0; h < NH; h++) acc[h] += hs[h*ES + e] * we;
            }
            #pragma unroll
            for (int h = 0; h < NH; h++) kqv_s[h*192 + tid] = acc[h];
        }
        __syncthreads();

        // ---- xd = 0.5 * ||z||^2 for k and q per head (16 reductions) ----
        {
            int grp = tid >> 4, l16 = tid & 15;   // grp: h*2 + (0=k,1=q)
            int h = grp >> 1, which = grp & 1;
            const float* base = kqv_s + h*192 + which*64;
            float sm = 0.f;
            #pragma unroll
            for (int j = 0; j < 4; j++) { float z = base[l16 + 16*j]; sm += z*z; }
            #pragma unroll
            for (int o = 8; o; o >>= 1) sm += __shfl_xor_sync(0xffffffffu, sm, o, 16);
            if (l16 == 0) xd_s[grp] = 0.5f * sm;
        }
        __syncthreads();

        // ---- features: kp/qp = exp(w.z - xd)/sqrt(M); also store v ----
        {
            int h = tid >> 5, m = tid & 31;
            const float* kb = kqv_s + h*192;
            float ak = 0.f, aq = 0.f;
            #pragma unroll
            for (int e = 0; e < ES; e++) {
                float wv = ws[e*MF + m];
                ak += kb[e]      * wv;
                aq += kb[64 + e] * wv;
            }
            float kpv = expf(ak - xd_s[h*2 + 0]) * RSQRT_MF;
            float qpv = expf(aq - xd_s[h*2 + 1]) * RSQRT_MF;
            size_t o = (tok*NH + h)*MF + m;
            g_kp[o] = kpv; g_qp[o] = qpv;
            g_v[tok*EMBD + tid]       = kqv_s[(tid >> 6)*192 + 128 + (tid & 63)];
            g_v[tok*EMBD + tid + 256] = kqv_s[((tid + 256) >> 6)*192 + 128 + (tid & 63)];
        }
        // next-iteration writes are sync-protected; no trailing barrier needed
    }
}

// ---------------- zero init for kptv / ks ----------------
__global__ void k_zero()
{
    int i = blockIdx.x * blockDim.x + threadIdx.x;
    if (i < BQ*NH*MF*ES) g_kptv[i] = 0.f;
    if (i < BQ*NH*MF)    g_ks[i]   = 0.f;
}

// ---------------- K2: kptv[b,h,m,e] = sum_t v*kp ; ks = sum_t kp --------
#define K2_CH   8
#define K2_TOKS (TQ/K2_CH)   /* 512 */
__global__ __launch_bounds__(256) void k2_kptv()
{
    int bh = blockIdx.x;      // 0..63
    int chunk = blockIdx.y;   // 0..7
    int b = bh >> 3, h = bh & 7;
    __shared__ float kp_s[8][MF];
    __shared__ float v_s[8][ES];
    int tid = threadIdx.x;
    int g = tid >> 5, m = tid & 31;
    float acc[8] = {0,0,0,0,0,0,0,0};
    float ksacc = 0.f;
    int t0 = chunk * K2_TOKS;

    for (int tb = 0; tb < K2_TOKS; tb += 8) {
        for (int li = tid; li < 8*96; li += 256) {
            int tk = li / 96, j = li % 96;
            size_t tok = (size_t)b*TQ + t0 + tb + tk;
            if (j < 32) kp_s[tk][j]     = g_kp[(tok*NH + h)*MF + j];
            else        v_s[tk][j - 32] = g_v[tok*EMBD + h*ES + (j - 32)];
        }
        __syncthreads();
        #pragma unroll
        for (int tk = 0; tk < 8; tk++) {
            float kv = kp_s[tk][m];
            if (g == 0) ksacc += kv;
            #pragma unroll
            for (int i = 0; i < 8; i++) acc[i] += v_s[tk][g*8 + i] * kv;
        }
        __syncthreads();
    }
    #pragma unroll
    for (int i = 0; i < 8; i++)
        atomicAdd(&g_kptv[(bh*MF + m)*ES + g*8 + i], acc[i]);
    if (g == 0) atomicAdd(&g_ks[bh*MF + m], ksacc);
}

// ---------------- K3: y = (qp . kptv) / (qp . ks) ----------------
#define K3_TOK 128
#define K3_SMEM ((NH*MF*ES + 256 + 256 + 8) * 4)
__global__ __launch_bounds__(256) void k3_y()
{
    extern __shared__ float sh[];
    float* kptv_s = sh;                 // [h][m][e]  8*32*64
    float* ks_s   = sh + NH*MF*ES;      // 256
    float* qp_s   = ks_s + 256;         // 256
    float* invD   = qp_s + 256;         // 8

    int b  = blockIdx.y;
    int t0 = blockIdx.x * K3_TOK;
    int tid = threadIdx.x;

    for (int i = tid; i < NH*MF*ES; i += 256) kptv_s[i] = g_kptv[b*NH*MF*ES + i];
    ks_s[tid] = g_ks[b*NH*MF + tid];
    __syncthreads();

    for (int it = 0; it < K3_TOK; it++) {
        size_t tok = (size_t)b*TQ + t0 + it;
        qp_s[tid] = g_qp[tok*NH*MF + tid];
        __syncthreads();
        int wd = tid >> 5, lane = tid & 31;
        float p = qp_s[wd*32 + lane] * ks_s[wd*32 + lane];
        #pragma unroll
        for (int o = 16; o; o >>= 1) p += __shfl_xor_sync(0xffffffffu, p, o);
        if (lane == 0) invD[wd] = 1.0f / p;
        __syncthreads();
        #pragma unroll
        for (int r = 0; r < 2; r++) {
            int ef = tid + r*256;
            int h = ef >> 6, e = ef & 63;
            const float* kb = kptv_s + h*MF*ES;   // [m][e]
            const float* qb = qp_s + h*MF;
            float sum = 0.f;
            #pragma unroll
            for (int mm = 0; mm < MF; mm++) sum += qb[mm] * kb[mm*ES + e];
            g_y[tok*EMBD + ef] = sum * invD[h];
        }
        __syncthreads();
    }
}

// ---------------- K5: LN2 on x1 -> h2 ----------------
__global__ __launch_bounds__(256) void k5_ln2(
    const float* __restrict__ g2, const float* __restrict__ bb2)
{
    __shared__ float red[16];
    __shared__ float mu_s, rs_s;
    size_t tok = blockIdx.x;
    const float* xr = g_x1 + tok*EMBD;
    float* hr = g_h2 + tok*EMBD;
    int tid = threadIdx.x;
    float v0 = xr[tid], v1 = xr[tid + 256];
    float s = v0 + v1, ss = v0*v0 + v1*v1;
    #pragma unroll
    for (int o = 16; o; o >>= 1) {
        s  += __shfl_xor_sync(0xffffffffu, s,  o);
        ss += __shfl_xor_sync(0xffffffffu, ss, o);
    }
    if ((tid & 31) == 0) { red[tid>>5] = s; red[8 + (tid>>5)] = ss; }
    __syncthreads();
    if (tid == 0) {
        float ts = 0, tss = 0;
        for (int i = 0; i < 8; i++) { ts += red[i]; tss += red[8+i]; }
        float mu = ts / EMBD;
        mu_s = mu;
        rs_s = rsqrtf(tss/EMBD - mu*mu + LN_EPS);
    }
    __syncthreads();
    float mu = mu_s, rs = rs_s;
    hr[tid]       = (v0 - mu) * rs * g2[tid]       + bb2[tid];
    hr[tid + 256] = (v1 - mu) * rs * g2[tid + 256] + bb2[tid + 256];
}

// ---------------- tiled SGEMM: C[m,n] = A[m,:] . W[n,:] + bias (+gelu)(+res) --
template<bool GELU, bool RES>
__global__ __launch_bounds__(256) void gemm_kernel(
    const float* __restrict__ A,    // [M,K]
    const float* __restrict__ W,    // [N,K]
    const float* __restrict__ bias, // [N]
    const float* __restrict__ res,  // [M,N] or nullptr
    float* __restrict__ C,          // [M,N]
    int N, int K)
{
    __shared__ float As[8][128];
    __shared__ float Bs[8][128];
    int tid = threadIdx.x;
    int m0 = blockIdx.y * 128;
    int n0 = blockIdx.x * 128;
    int tx = tid & 15, ty = tid >> 4;
    float c[8][8];
    #pragma unroll
    for (int i = 0; i < 8; i++)
        #pragma unroll
        for (int j = 0; j < 8; j++) c[i][j] = 0.f;

    int ar = tid >> 1;
    int ak = (tid & 1) * 4;
    const float* Aptr = A + (size_t)(m0 + ar)*K + ak;
    const float* Wptr = W + (size_t)(n0 + ar)*K + ak;

    for (int kt = 0; kt < K; kt += 8) {
        float4 av = *(const float4*)(Aptr + kt);
        float4 bv = *(const float4*)(Wptr + kt);
        __syncthreads();
        As[ak+0][ar] = av.x; As[ak+1][ar] = av.y; As[ak+2][ar] = av.z; As[ak+3][ar] = av.w;
        Bs[ak+0][ar] = bv.x; Bs[ak+1][ar] = bv.y; Bs[ak+2][ar] = bv.z; Bs[ak+3][ar] = bv.w;
        __syncthreads();
        #pragma unroll
        for (int k = 0; k < 8; k++) {
            float a[8], b[8];
            #pragma unroll
            for (int i = 0; i < 8; i++) a[i] = As[k][ty*8 + i];
            #pragma unroll
            for (int j = 0; j < 8; j++) b[j] = Bs[k][tx*8 + j];
            #pragma unroll
            for (int i = 0; i < 8; i++)
                #pragma unroll
                for (int j = 0; j < 8; j++) c[i][j] += a[i] * b[j];
        }
    }

    #pragma unroll
    for (int i = 0; i < 8; i++) {
        size_t row = m0 + ty*8 + i;
        #pragma unroll
        for (int j = 0; j < 8; j++) {
            int col = n0 + tx*8 + j;
            float val = c[i][j] + bias[col];
            if (GELU) val = 0.5f * val * (1.0f + erff(val * 0.70710678118654752f));
            if (RES)  val += res[row*(size_t)N + col];
            C[row*(size_t)N + col] = val;
        }
    }
}

// ---------------- launch ----------------
extern "C" void kernel_launch(void* const* d_in, const int* in_sizes, int n_in,
                              void* d_out, int out_size)
{
    const float* x      = (const float*)d_in[0];
    const float* w      = (const float*)d_in[1];
    const float* kqv_w  = (const float*)d_in[2];
    const float* kqv_b  = (const float*)d_in[3];
    const float* proj_w = (const float*)d_in[4];
    const float* proj_b = (const float*)d_in[5];
    const float* ln1_g  = (const float*)d_in[6];
    const float* ln1_b  = (const float*)d_in[7];
    const float* ln2_g  = (const float*)d_in[8];
    const float* ln2_b  = (const float*)d_in[9];
    const float* mlp_w1 = (const float*)d_in[10];
    const float* mlp_b1 = (const float*)d_in[11];
    const float* mlp_w2 = (const float*)d_in[12];
    const float* mlp_b2 = (const float*)d_in[13];
    float* out = (float*)d_out;

    // resolve scratch symbol addresses (pure queries; capture-safe)
    void *py, *px1, *ph2, *phid;
    cudaGetSymbolAddress(&py,  g_y);
    cudaGetSymbolAddress(&px1, g_x1);
    cudaGetSymbolAddress(&ph2, g_h2);
    cudaGetSymbolAddress(&phid, g_hid);

    cudaFuncSetAttribute(k3_y, cudaFuncAttributeMaxDynamicSharedMemorySize, K3_SMEM);

    // attention front-end
    k1_ln_kqv_feat<<<BT/K1_TOK, 256>>>(x, w, kqv_w, kqv_b, ln1_g, ln1_b);
    k_zero<<<(BQ*NH*MF*ES + 255)/256, 256>>>();
    k2_kptv<<<dim3(BQ*NH, K2_CH), 256>>>();
    k3_y<<<dim3(TQ/K3_TOK, BQ), 256, K3_SMEM>>>();

    // proj GEMM + residual -> x1
    gemm_kernel<false, true><<<dim3(EMBD/128, BT/128), 256>>>(
        (const float*)py, proj_w, proj_b, x, (float*)px1, EMBD, EMBD);

    // LN2
    k5_ln2<<<BT, 256>>>(ln2_g, ln2_b);

    // MLP1 (gelu) -> hid
    gemm_kernel<true, false><<<dim3(HID/128, BT/128), 256>>>(
        (const float*)ph2, mlp_w1, mlp_b1, nullptr, (float*)phid, HID, EMBD);

    // MLP2 + residual -> out
    gemm_kernel<false, true><<<dim3(EMBD/128, BT/128), 256>>>(
        (const float*)phid, mlp_w2, mlp_b2, (const float*)px1, out, EMBD, HID);
}

// round 8
// speedup vs baseline: 1.3154x; 1.3154x over previous
#include <cuda_runtime.h>
#include <math.h>
#include <stdint.h>

#define BQ   8
#define TQ   4096
#define NH   8
#define ES   64
#define EMBD 512
#define MF   32
#define BT   (BQ*TQ)      /* 32768 tokens */
#define HID  2048
#define LN_EPS 1e-5f
#define RSQRT_MF 0.17677669529663687f  /* 1/sqrt(32) */

// ---------------- scratch (device globals: alloc-free) ----------------
__device__ float g_qp[(size_t)BT*NH*MF];     // [tok][h][m]
__device__ float g_kp[(size_t)BT*NH*MF];
__device__ float g_v [(size_t)BT*EMBD];      // [tok][h*64+e]
__device__ float g_y [(size_t)BT*EMBD];      // tf32-rounded
__device__ float g_x1[(size_t)BT*EMBD];      // x + attn (full fp32)
__device__ float g_h2[(size_t)BT*EMBD];      // LN2(x1), tf32-rounded
__device__ float g_hid[(size_t)BT*HID];      // gelu(mlp1), tf32-rounded
__device__ float g_kptv[BQ*NH*MF*ES];        // [b][h][m][e]
__device__ float g_ks[BQ*NH*MF];             // [b][h][m]
__device__ float g_wp[EMBD*EMBD];            // tf32-rounded weights
__device__ float g_w1[(size_t)HID*EMBD];
__device__ float g_w2[(size_t)EMBD*HID];

// ---------------- tf32 round-to-nearest ----------------
__device__ __forceinline__ float tf32r(float x) {
    uint32_t u;
    asm("cvt.rna.tf32.f32 %0, %1;" : "=r"(u) : "f"(x));
    return __uint_as_float(u);
}

__global__ __launch_bounds__(256) void k_round(const float* __restrict__ s,
                                               float* __restrict__ d, int n)
{
    int i = blockIdx.x * 256 + threadIdx.x;
    if (i < n) d[i] = tf32r(s[i]);
}

// ---------------- K1: LN1 + kqv + random features ----------------
#define K1_TOK 32
__global__ __launch_bounds__(256) void k1_ln_kqv_feat(
    const float* __restrict__ x, const float* __restrict__ w,
    const float* __restrict__ kqv_w, const float* __restrict__ kqv_b,
    const float* __restrict__ g1, const float* __restrict__ b1)
{
    __shared__ float hs[EMBD];
    __shared__ float kqv_s[NH*192];
    __shared__ float ws[ES*MF];      // ws[e*MF+m], transposed w
    __shared__ float xd_s[16];
    __shared__ float red_s[16];
    __shared__ float mu_s, rstd_s;

    int tid = threadIdx.x;

    for (int i = tid; i < ES*MF; i += 256) {
        int m = i / ES, e = i % ES;
        ws[e*MF + m] = w[i];
    }
    float wrow[ES];
    float bf = 0.f;
    if (tid < 192) {
        bf = kqv_b[tid];
        #pragma unroll
        for (int e = 0; e < ES; e++) wrow[e] = kqv_w[tid*ES + e];
    }
    __syncthreads();

    for (int it = 0; it < K1_TOK; it++) {
        size_t tok = (size_t)blockIdx.x * K1_TOK + it;
        const float* xr = x + tok * EMBD;

        float v0 = xr[tid], v1 = xr[tid + 256];
        float s = v0 + v1, ss = v0*v0 + v1*v1;
        #pragma unroll
        for (int o = 16; o; o >>= 1) {
            s  += __shfl_xor_sync(0xffffffffu, s,  o);
            ss += __shfl_xor_sync(0xffffffffu, ss, o);
        }
        if ((tid & 31) == 0) { red_s[tid>>5] = s; red_s[8 + (tid>>5)] = ss; }
        __syncthreads();
        if (tid == 0) {
            float ts = 0, tss = 0;
            for (int i = 0; i < 8; i++) { ts += red_s[i]; tss += red_s[8+i]; }
            float mu = ts / EMBD;
            mu_s = mu;
            rstd_s = rsqrtf(tss/EMBD - mu*mu + LN_EPS);
        }
        __syncthreads();
        float mu = mu_s, rstd = rstd_s;
        hs[tid]       = (v0 - mu) * rstd * g1[tid]       + b1[tid];
        hs[tid + 256] = (v1 - mu) * rstd * g1[tid + 256] + b1[tid + 256];
        __syncthreads();

        if (tid < 192) {
            float acc[NH];
            #pragma unroll
            for (int h = 0; h < NH; h++) acc[h] = bf;
            #pragma unroll
            for (int e = 0; e < ES; e++) {
                float we = wrow[e];
                #pragma unroll
                for (int h = 0; h < NH; h++) acc[h] += hs[h*ES + e] * we;
            }
            #pragma unroll
            for (int h = 0; h < NH; h++) kqv_s[h*192 + tid] = acc[h];
        }
        __syncthreads();

        {
            int grp = tid >> 4, l16 = tid & 15;
            int h = grp >> 1, which = grp & 1;
            const float* base = kqv_s + h*192 + which*64;
            float sm = 0.f;
            #pragma unroll
            for (int j = 0; j < 4; j++) { float z = base[l16 + 16*j]; sm += z*z; }
            #pragma unroll
            for (int o = 8; o; o >>= 1) sm += __shfl_xor_sync(0xffffffffu, sm, o, 16);
            if (l16 == 0) xd_s[grp] = 0.5f * sm;
        }
        __syncthreads();

        {
            int h = tid >> 5, m = tid & 31;
            const float* kb = kqv_s + h*192;
            float ak = 0.f, aq = 0.f;
            #pragma unroll
            for (int e = 0; e < ES; e++) {
                float wv = ws[e*MF + m];
                ak += kb[e]      * wv;
                aq += kb[64 + e] * wv;
            }
            float kpv = expf(ak - xd_s[h*2 + 0]) * RSQRT_MF;
            float qpv = expf(aq - xd_s[h*2 + 1]) * RSQRT_MF;
            size_t o = (tok*NH + h)*MF + m;
            g_kp[o] = kpv; g_qp[o] = qpv;
            g_v[tok*EMBD + tid]       = kqv_s[(tid >> 6)*192 + 128 + (tid & 63)];
            g_v[tok*EMBD + tid + 256] = kqv_s[((tid + 256) >> 6)*192 + 128 + (tid & 63)];
        }
    }
}

// ---------------- zero init for kptv / ks ----------------
__global__ void k_zero()
{
    int i = blockIdx.x * blockDim.x + threadIdx.x;
    if (i < BQ*NH*MF*ES) g_kptv[i] = 0.f;
    if (i < BQ*NH*MF)    g_ks[i]   = 0.f;
}

// ---------------- K2: kptv[b,h,m,e] = sum_t v*kp ; ks = sum_t kp --------
#define K2_CH   8
#define K2_TOKS (TQ/K2_CH)
__global__ __launch_bounds__(256) void k2_kptv()
{
    int bh = blockIdx.x;
    int chunk = blockIdx.y;
    int b = bh >> 3, h = bh & 7;
    __shared__ float kp_s[8][MF];
    __shared__ float v_s[8][ES];
    int tid = threadIdx.x;
    int g = tid >> 5, m = tid & 31;
    float acc[8] = {0,0,0,0,0,0,0,0};
    float ksacc = 0.f;
    int t0 = chunk * K2_TOKS;

    for (int tb = 0; tb < K2_TOKS; tb += 8) {
        for (int li = tid; li < 8*96; li += 256) {
            int tk = li / 96, j = li % 96;
            size_t tok = (size_t)b*TQ + t0 + tb + tk;
            if (j < 32) kp_s[tk][j]     = g_kp[(tok*NH + h)*MF + j];
            else        v_s[tk][j - 32] = g_v[tok*EMBD + h*ES + (j - 32)];
        }
        __syncthreads();
        #pragma unroll
        for (int tk = 0; tk < 8; tk++) {
            float kv = kp_s[tk][m];
            if (g == 0) ksacc += kv;
            #pragma unroll
            for (int i = 0; i < 8; i++) acc[i] += v_s[tk][g*8 + i] * kv;
        }
        __syncthreads();
    }
    #pragma unroll
    for (int i = 0; i < 8; i++)
        atomicAdd(&g_kptv[(bh*MF + m)*ES + g*8 + i], acc[i]);
    if (g == 0) atomicAdd(&g_ks[bh*MF + m], ksacc);
}

// ---------------- K3: y = (qp . kptv) / (qp . ks), tf32-rounded --------
#define K3_TOK 128
#define K3_SMEM ((NH*MF*ES + 256 + 256 + 8) * 4)
__global__ __launch_bounds__(256) void k3_y()
{
    extern __shared__ float sh[];
    float* kptv_s = sh;
    float* ks_s   = sh + NH*MF*ES;
    float* qp_s   = ks_s + 256;
    float* invD   = qp_s + 256;

    int b  = blockIdx.y;
    int t0 = blockIdx.x * K3_TOK;
    int tid = threadIdx.x;

    for (int i = tid; i < NH*MF*ES; i += 256) kptv_s[i] = g_kptv[b*NH*MF*ES + i];
    ks_s[tid] = g_ks[b*NH*MF + tid];
    __syncthreads();

    for (int it = 0; it < K3_TOK; it++) {
        size_t tok = (size_t)b*TQ + t0 + it;
        qp_s[tid] = g_qp[tok*NH*MF + tid];
        __syncthreads();
        int wd = tid >> 5, lane = tid & 31;
        float p = qp_s[wd*32 + lane] * ks_s[wd*32 + lane];
        #pragma unroll
        for (int o = 16; o; o >>= 1) p += __shfl_xor_sync(0xffffffffu, p, o);
        if (lane == 0) invD[wd] = 1.0f / p;
        __syncthreads();
        #pragma unroll
        for (int r = 0; r < 2; r++) {
            int ef = tid + r*256;
            int h = ef >> 6, e = ef & 63;
            const float* kb = kptv_s + h*MF*ES;
            const float* qb = qp_s + h*MF;
            float sum = 0.f;
            #pragma unroll
            for (int mm = 0; mm < MF; mm++) sum += qb[mm] * kb[mm*ES + e];
            g_y[tok*EMBD + ef] = tf32r(sum * invD[h]);
        }
        __syncthreads();
    }
}

// ---------------- K5: LN2 on x1 -> h2 (tf32-rounded) ----------------
__global__ __launch_bounds__(256) void k5_ln2(
    const float* __restrict__ g2, const float* __restrict__ bb2)
{
    __shared__ float red[16];
    __shared__ float mu_s, rs_s;
    size_t tok = blockIdx.x;
    const float* xr = g_x1 + tok*EMBD;
    float* hr = g_h2 + tok*EMBD;
    int tid = threadIdx.x;
    float v0 = xr[tid], v1 = xr[tid + 256];
    float s = v0 + v1, ss = v0*v0 + v1*v1;
    #pragma unroll
    for (int o = 16; o; o >>= 1) {
        s  += __shfl_xor_sync(0xffffffffu, s,  o);
        ss += __shfl_xor_sync(0xffffffffu, ss, o);
    }
    if ((tid & 31) == 0) { red[tid>>5] = s; red[8 + (tid>>5)] = ss; }
    __syncthreads();
    if (tid == 0) {
        float ts = 0, tss = 0;
        for (int i = 0; i < 8; i++) { ts += red[i]; tss += red[8+i]; }
        float mu = ts / EMBD;
        mu_s = mu;
        rs_s = rsqrtf(tss/EMBD - mu*mu + LN_EPS);
    }
    __syncthreads();
    float mu = mu_s, rs = rs_s;
    hr[tid]       = tf32r((v0 - mu) * rs * g2[tid]       + bb2[tid]);
    hr[tid + 256] = tf32r((v1 - mu) * rs * g2[tid + 256] + bb2[tid + 256]);
}

// =====================================================================
// tf32 tensor-core GEMM via mma.sync.m16n8k8 (valid on plain sm_103 PTX)
// C[m,n] = sum_k A[m,k]*B[n,k] + bias[n] (+gelu)(+res)(+round)
// 128x128 tile, 8 warps (2M x 4N, warp tile 64x32), K-chunk 32,
// cp.async 2-stage pipeline, padded K-contiguous smem tiles.
// =====================================================================
#define GT_M 128
#define GT_N 128
#define GK   32
#define TPAD 36                                /* floats per row in smem */
#define STAGE_FLOATS (2 * 128 * TPAD)          /* A tile + B tile */
#define GEMM_SMEM    (2 * STAGE_FLOATS * 4)    /* 73728 B */

__device__ __forceinline__ uint32_t smem_u32(const void* p) {
    uint32_t a;
    asm("{ .reg .u64 t; cvta.to.shared.u64 t, %1; cvt.u32.u64 %0, t; }"
        : "=r"(a) : "l"(p));
    return a;
}
__device__ __forceinline__ void cp16(uint32_t s, const void* g) {
    asm volatile("cp.async.cg.shared.global [%0], [%1], 16;" :: "r"(s), "l"(g));
}
__device__ __forceinline__ void cp_commit() { asm volatile("cp.async.commit_group;"); }
template<int N> __device__ __forceinline__ void cp_wait() {
    asm volatile("cp.async.wait_group %0;" :: "n"(N));
}
__device__ __forceinline__ void mma1688(float* c, const uint32_t* a, const uint32_t* b) {
    asm volatile("mma.sync.aligned.m16n8k8.row.col.f32.tf32.tf32.f32 "
        "{%0,%1,%2,%3}, {%4,%5,%6,%7}, {%8,%9}, {%0,%1,%2,%3};"
        : "+f"(c[0]), "+f"(c[1]), "+f"(c[2]), "+f"(c[3])
        : "r"(a[0]), "r"(a[1]), "r"(a[2]), "r"(a[3]), "r"(b[0]), "r"(b[1]));
}

template<bool GELU, bool RES, bool ROUND>
__global__ __launch_bounds__(256) void tc_gemm(
    const float* __restrict__ A,    // [M,K] tf32-rounded
    const float* __restrict__ B,    // [N,K] tf32-rounded
    const float* __restrict__ bias, // [N]
    const float* __restrict__ res,  // [M,N] or nullptr
    float* __restrict__ C,          // [M,N]
    int N, int K)
{
    extern __shared__ __align__(16) float smf[];
    uint32_t sb = smem_u32(smf);
    int tid  = threadIdx.x;
    int warp = tid >> 5, lane = tid & 31;
    int gid  = lane >> 2, tig = lane & 3;
    int m0 = blockIdx.y * GT_M;
    int n0 = blockIdx.x * GT_N;
    int mw = (warp >> 2) * 64;       // warp M offset (0 or 64)
    int nw = (warp & 3) * 32;        // warp N offset

    // ---- cp.async addressing: thread -> (row, 64B half-row) ----
    int lrow = tid >> 1;             // 0..127
    int lseg = (tid & 1) * 16;       // float offset 0 or 16
    const char* gA = (const char*)(A + (size_t)(m0 + lrow) * K + lseg);
    const char* gB = (const char*)(B + (size_t)(n0 + lrow) * K + lseg);
    uint32_t sA = sb + (lrow * TPAD + lseg) * 4;
    uint32_t sB = sA + 128 * TPAD * 4;

    float acc[4][4][4];
    #pragma unroll
    for (int i = 0; i < 4; i++)
        #pragma unroll
        for (int j = 0; j < 4; j++)
            #pragma unroll
            for (int r = 0; r < 4; r++) acc[i][j][r] = 0.f;

    const int NC = K / GK;

    auto load_chunk = [&](int kc, int s) {
        uint32_t so = s * STAGE_FLOATS * 4;
        size_t go = (size_t)kc * (GK * 4);
        #pragma unroll
        for (int i = 0; i < 4; i++) cp16(sA + so + i * 16, gA + go + i * 16);
        #pragma unroll
        for (int i = 0; i < 4; i++) cp16(sB + so + i * 16, gB + go + i * 16);
        cp_commit();
    };

    load_chunk(0, 0);

    for (int c = 0; c < NC; c++) {
        int s = c & 1;
        if (c + 1 < NC) { load_chunk(c + 1, s ^ 1); cp_wait<1>(); }
        else           { cp_wait<0>(); }
        __syncthreads();

        const float* As = smf + s * STAGE_FLOATS;
        const float* Bs = As + 128 * TPAD;

        #pragma unroll
        for (int kk = 0; kk < GK; kk += 8) {
            uint32_t a[4][4], b[4][2];
            #pragma unroll
            for (int mt = 0; mt < 4; mt++) {
                int r = mw + mt * 16 + gid;
                a[mt][0] = __float_as_uint(As[r * TPAD + kk + tig]);
                a[mt][1] = __float_as_uint(As[(r + 8) * TPAD + kk + tig]);
                a[mt][2] = __float_as_uint(As[r * TPAD + kk + tig + 4]);
                a[mt][3] = __float_as_uint(As[(r + 8) * TPAD + kk + tig + 4]);
            }
            #pragma unroll
            for (int nt = 0; nt < 4; nt++) {
                int r = nw + nt * 8 + gid;
                b[nt][0] = __float_as_uint(Bs[r * TPAD + kk + tig]);
                b[nt][1] = __float_as_uint(Bs[r * TPAD + kk + tig + 4]);
            }
            #pragma unroll
            for (int mt = 0; mt < 4; mt++)
                #pragma unroll
                for (int nt = 0; nt < 4; nt++)
                    mma1688(acc[mt][nt], a[mt], b[nt]);
        }
        __syncthreads();
    }

    // ---- epilogue: C fragment layout, float2 stores ----
    #pragma unroll
    for (int mt = 0; mt < 4; mt++) {
        #pragma unroll
        for (int half = 0; half < 2; half++) {
            size_t row = (size_t)(m0 + mw + mt * 16 + gid + half * 8);
            #pragma unroll
            for (int nt = 0; nt < 4; nt++) {
                int col = n0 + nw + nt * 8 + tig * 2;
                float vx = acc[mt][nt][half * 2 + 0] + bias[col];
                float vy = acc[mt][nt][half * 2 + 1] + bias[col + 1];
                if (GELU) {
                    vx = 0.5f * vx * (1.0f + erff(vx * 0.70710678118654752f));
                    vy = 0.5f * vy * (1.0f + erff(vy * 0.70710678118654752f));
                }
                if (RES) {
                    float2 rv = *(const float2*)(res + row * N + col);
                    vx += rv.x; vy += rv.y;
                }
                if (ROUND) { vx = tf32r(vx); vy = tf32r(vy); }
                float2 o; o.x = vx; o.y = vy;
                *(float2*)(C + row * N + col) = o;
            }
        }
    }
}

// ---------------- launch ----------------
extern "C" void kernel_launch(void* const* d_in, const int* in_sizes, int n_in,
                              void* d_out, int out_size)
{
    const float* x      = (const float*)d_in[0];
    const float* w      = (const float*)d_in[1];
    const float* kqv_w  = (const float*)d_in[2];
    const float* kqv_b  = (const float*)d_in[3];
    const float* proj_w = (const float*)d_in[4];
    const float* proj_b = (const float*)d_in[5];
    const float* ln1_g  = (const float*)d_in[6];
    const float* ln1_b  = (const float*)d_in[7];
    const float* ln2_g  = (const float*)d_in[8];
    const float* ln2_b  = (const float*)d_in[9];
    const float* mlp_w1 = (const float*)d_in[10];
    const float* mlp_b1 = (const float*)d_in[11];
    const float* mlp_w2 = (const float*)d_in[12];
    const float* mlp_b2 = (const float*)d_in[13];
    float* out = (float*)d_out;

    void *py, *px1, *ph2, *phid, *pwp, *pw1, *pw2;
    cudaGetSymbolAddress(&py,  g_y);
    cudaGetSymbolAddress(&px1, g_x1);
    cudaGetSymbolAddress(&ph2, g_h2);
    cudaGetSymbolAddress(&phid, g_hid);
    cudaGetSymbolAddress(&pwp, g_wp);
    cudaGetSymbolAddress(&pw1, g_w1);
    cudaGetSymbolAddress(&pw2, g_w2);

    cudaFuncSetAttribute(k3_y, cudaFuncAttributeMaxDynamicSharedMemorySize, K3_SMEM);
    cudaFuncSetAttribute(tc_gemm<false, true, false>, cudaFuncAttributeMaxDynamicSharedMemorySize, GEMM_SMEM);
    cudaFuncSetAttribute(tc_gemm<true, false, true>,  cudaFuncAttributeMaxDynamicSharedMemorySize, GEMM_SMEM);

    // weight prep: tf32-round once per launch (cheap)
    k_round<<<(EMBD*EMBD + 255)/256, 256>>>(proj_w, (float*)pwp, EMBD*EMBD);
    k_round<<<(HID*EMBD + 255)/256, 256>>>(mlp_w1, (float*)pw1, HID*EMBD);
    k_round<<<(EMBD*HID + 255)/256, 256>>>(mlp_w2, (float*)pw2, EMBD*HID);

    // attention front-end
    k1_ln_kqv_feat<<<BT/K1_TOK, 256>>>(x, w, kqv_w, kqv_b, ln1_g, ln1_b);
    k_zero<<<(BQ*NH*MF*ES + 255)/256, 256>>>();
    k2_kptv<<<dim3(BQ*NH, K2_CH), 256>>>();
    k3_y<<<dim3(TQ/K3_TOK, BQ), 256, K3_SMEM>>>();

    // proj GEMM + residual -> x1 (full fp32)
    tc_gemm<false, true, false><<<dim3(EMBD/GT_N, BT/GT_M), 256, GEMM_SMEM>>>(
        (const float*)py, (const float*)pwp, proj_b, x, (float*)px1, EMBD, EMBD);

    // LN2 -> h2 (tf32-rounded)
    k5_ln2<<<BT, 256>>>(ln2_g, ln2_b);

    // MLP1 + gelu -> hid (tf32-rounded)
    tc_gemm<true, false, true><<<dim3(HID/GT_N, BT/GT_M), 256, GEMM_SMEM>>>(
        (const float*)ph2, (const float*)pw1, mlp_b1, nullptr, (float*)phid, HID, EMBD);

    // MLP2 + residual -> out (full fp32)
    tc_gemm<false, true, false><<<dim3(EMBD/GT_N, BT/GT_M), 256, GEMM_SMEM>>>(
        (const float*)phid, (const float*)pw2, mlp_b2, (const float*)px1, out, EMBD, HID);
}

// round 13
// speedup vs baseline: 3.3982x; 2.5834x over previous
#include <cuda_runtime.h>
#include <cuda_fp16.h>
#include <math.h>
#include <stdint.h>

#define BQ   8
#define TQ   4096
#define NH   8
#define ES   64
#define EMBD 512
#define MF   32
#define BT   (BQ*TQ)      /* 32768 tokens */
#define ROWS ((size_t)BT*NH)  /* 262144 (t,h) rows */
#define HID  2048
#define LN_EPS 1e-5f
#define RSQRT_MF 0.17677669529663687f  /* 1/sqrt(32) */

// ---------------- scratch (device globals: alloc-free) ----------------
__device__ __half g_h1[(size_t)BT*EMBD];      // LN1(x), half  [row=(t,h)][64]
__device__ float  g_kqv[ROWS*256];            // kqv GEMM out (k|q|v|pad) fp32
__device__ float  g_qp[ROWS*MF];              // [row][m]
__device__ float  g_kp[ROWS*MF];
__device__ __half g_y [(size_t)BT*EMBD];      // attn out, half
__device__ float  g_x1[(size_t)BT*EMBD];      // x + attn (fp32)
__device__ __half g_h2[(size_t)BT*EMBD];      // LN2(x1), half
__device__ __half g_hid[(size_t)BT*HID];      // gelu(mlp1), half
__device__ float  g_kptv[BQ*NH*MF*ES];        // [b][h][m][e]
__device__ float  g_ks[BQ*NH*MF];             // [b][h][m]
__device__ __half g_wkqv[256*ES];             // padded kqv_w, half
__device__ float  g_bkqv[256];                // padded kqv_b
__device__ __half g_wp[EMBD*EMBD];            // half weights
__device__ __half g_w1[(size_t)HID*EMBD];
__device__ __half g_w2[(size_t)EMBD*HID];

// ---------------- weight prep ----------------
__global__ __launch_bounds__(256) void k_round_h(const float* __restrict__ s,
                                                 __half* __restrict__ d, int n)
{
    int i = blockIdx.x * 256 + threadIdx.x;
    if (i < n) d[i] = __float2half_rn(s[i]);
}

__global__ __launch_bounds__(256) void k_prep_kqv(const float* __restrict__ wq,
                                                  const float* __restrict__ bq)
{
    int i = blockIdx.x * 256 + threadIdx.x;
    if (i < 256 * ES) {
        int r = i >> 6, c = i & 63;
        g_wkqv[i] = (r < 192) ? __float2half_rn(wq[r*ES + c]) : __half(0.f);
    }
    if (i < 256) g_bkqv[i] = (i < 192) ? bq[i] : 0.f;
}

// ---------------- LayerNorm (2 elems/thread, half2 out) ----------------
__device__ __forceinline__ void ln_core(const float* __restrict__ xr, int tid,
                                        float* red, float& mu, float& rs,
                                        float& v0, float& v1)
{
    float2 v = *(const float2*)(xr + 2*tid);
    v0 = v.x; v1 = v.y;
    float s = v0 + v1, ss = v0*v0 + v1*v1;
    #pragma unroll
    for (int o = 16; o; o >>= 1) {
        s  += __shfl_xor_sync(0xffffffffu, s,  o);
        ss += __shfl_xor_sync(0xffffffffu, ss, o);
    }
    if ((tid & 31) == 0) { red[tid>>5] = s; red[8 + (tid>>5)] = ss; }
    __syncthreads();
    if (tid == 0) {
        float ts = 0, tss = 0;
        #pragma unroll
        for (int i = 0; i < 8; i++) { ts += red[i]; tss += red[8+i]; }
        float m = ts / EMBD;
        red[16] = m;
        red[17] = rsqrtf(tss/EMBD - m*m + LN_EPS);
    }
    __syncthreads();
    mu = red[16]; rs = red[17];
}

__global__ __launch_bounds__(256) void k_ln1(const float* __restrict__ x,
                                             const float* __restrict__ g,
                                             const float* __restrict__ b)
{
    __shared__ float red[18];
    size_t tok = blockIdx.x;
    int tid = threadIdx.x;
    float mu, rs, v0, v1;
    ln_core(x + tok*EMBD, tid, red, mu, rs, v0, v1);
    float o0 = (v0 - mu) * rs * g[2*tid]     + b[2*tid];
    float o1 = (v1 - mu) * rs * g[2*tid + 1] + b[2*tid + 1];
    __half2 h; h.x = __float2half_rn(o0); h.y = __float2half_rn(o1);
    ((__half2*)g_h1)[tok*256 + tid] = h;
}

__global__ __launch_bounds__(256) void k_ln2(const float* __restrict__ g,
                                             const float* __restrict__ b)
{
    __shared__ float red[18];
    size_t tok = blockIdx.x;
    int tid = threadIdx.x;
    float mu, rs, v0, v1;
    ln_core(g_x1 + tok*EMBD, tid, red, mu, rs, v0, v1);
    float o0 = (v0 - mu) * rs * g[2*tid]     + b[2*tid];
    float o1 = (v1 - mu) * rs * g[2*tid + 1] + b[2*tid + 1];
    __half2 h; h.x = __float2half_rn(o0); h.y = __float2half_rn(o1);
    ((__half2*)g_h2)[tok*256 + tid] = h;
}

// ---------------- features: kp/qp = exp(w.z - 0.5||z||^2)/sqrt(M) ------
// block: 8 warps x 4 rows = 32 (t,h) rows
__global__ __launch_bounds__(256) void k_feat(const float* __restrict__ w)
{
    __shared__ float w_s[ES*MF];     // [e][m]
    __shared__ float zk_s[32][ES];
    __shared__ float zq_s[32][ES];
    int tid = threadIdx.x;
    size_t r0 = (size_t)blockIdx.x * 32;

    for (int i = tid; i < MF*ES; i += 256) {
        int m = i >> 6, e = i & 63;
        w_s[e*MF + m] = w[i];
    }
    #pragma unroll
    for (int p = 0; p < 16; p++) {
        int idx = tid + p*256;            // 0..4095
        int lr = idx >> 7, c = idx & 127;
        float v = g_kqv[(r0 + lr)*256 + c];
        if (c < 64) zk_s[lr][c] = v; else zq_s[lr][c - 64] = v;
    }
    __syncthreads();

    int wp = tid >> 5, m = tid & 31;
    #pragma unroll
    for (int j = 0; j < 4; j++) {
        int r = wp*4 + j;
        // xd via per-lane partial + warp reduce
        float zk0 = zk_s[r][m], zk1 = zk_s[r][m+32];
        float zq0 = zq_s[r][m], zq1 = zq_s[r][m+32];
        float xk = zk0*zk0 + zk1*zk1;
        float xq = zq0*zq0 + zq1*zq1;
        #pragma unroll
        for (int o = 16; o; o >>= 1) {
            xk += __shfl_xor_sync(0xffffffffu, xk, o);
            xq += __shfl_xor_sync(0xffffffffu, xq, o);
        }
        float ak = 0.f, aq = 0.f;
        #pragma unroll
        for (int e = 0; e < ES; e++) {
            float wv = w_s[e*MF + m];
            ak += zk_s[r][e] * wv;
            aq += zq_s[r][e] * wv;
        }
        size_t row = r0 + r;
        g_kp[row*MF + m] = expf(ak - 0.5f*xk) * RSQRT_MF;
        g_qp[row*MF + m] = expf(aq - 0.5f*xq) * RSQRT_MF;
    }
}

// ---------------- zero init for kptv / ks ----------------
__global__ void k_zero()
{
    int i = blockIdx.x * blockDim.x + threadIdx.x;
    if (i < BQ*NH*MF*ES) g_kptv[i] = 0.f;
    if (i < BQ*NH*MF)    g_ks[i]   = 0.f;
}

// ---------------- K2: kptv[b,h,m,e] = sum_t v*kp ; ks = sum_t kp --------
#define K2_CH   8
#define K2_TOKS (TQ/K2_CH)
__global__ __launch_bounds__(256) void k2_kptv()
{
    int bh = blockIdx.x;
    int chunk = blockIdx.y;
    int b = bh >> 3, h = bh & 7;
    __shared__ float kp_s[8][MF];
    __shared__ float v_s[8][ES];
    int tid = threadIdx.x;
    int g = tid >> 5, m = tid & 31;
    float acc[8] = {0,0,0,0,0,0,0,0};
    float ksacc = 0.f;
    int t0 = chunk * K2_TOKS;

    for (int tb = 0; tb < K2_TOKS; tb += 8) {
        for (int li = tid; li < 8*96; li += 256) {
            int tk = li / 96, j = li % 96;
            size_t tok = (size_t)b*TQ + t0 + tb + tk;
            size_t row = tok*NH + h;
            if (j < 32) kp_s[tk][j]     = g_kp[row*MF + j];
            else        v_s[tk][j - 32] = g_kqv[row*256 + 96 + j];  // v[e]=col 128+(j-32)
        }
        __syncthreads();
        #pragma unroll
        for (int tk = 0; tk < 8; tk++) {
            float kv = kp_s[tk][m];
            if (g == 0) ksacc += kv;
            #pragma unroll
            for (int i = 0; i < 8; i++) acc[i] += v_s[tk][g*8 + i] * kv;
        }
        __syncthreads();
    }
    #pragma unroll
    for (int i = 0; i < 8; i++)
        atomicAdd(&g_kptv[(bh*MF + m)*ES + g*8 + i], acc[i]);
    if (g == 0) atomicAdd(&g_ks[bh*MF + m], ksacc);
}

// ---------------- K3: y = (qp . kptv) / (qp . ks) -> half --------------
#define K3_TOK 128
#define K3_SMEM ((NH*MF*ES + 256 + 256 + 8) * 4)
__global__ __launch_bounds__(256) void k3_y()
{
    extern __shared__ float sh[];
    float* kptv_s = sh;
    float* ks_s   = sh + NH*MF*ES;
    float* qp_s   = ks_s + 256;
    float* invD   = qp_s + 256;

    int b  = blockIdx.y;
    int t0 = blockIdx.x * K3_TOK;
    int tid = threadIdx.x;

    for (int i = tid; i < NH*MF*ES; i += 256) kptv_s[i] = g_kptv[b*NH*MF*ES + i];
    ks_s[tid] = g_ks[b*NH*MF + tid];
    __syncthreads();

    for (int it = 0; it < K3_TOK; it++) {
        size_t tok = (size_t)b*TQ + t0 + it;
        qp_s[tid] = g_qp[tok*NH*MF + tid];
        __syncthreads();
        int wd = tid >> 5, lane = tid & 31;
        float p = qp_s[wd*32 + lane] * ks_s[wd*32 + lane];
        #pragma unroll
        for (int o = 16; o; o >>= 1) p += __shfl_xor_sync(0xffffffffu, p, o);
        if (lane == 0) invD[wd] = 1.0f / p;
        __syncthreads();
        #pragma unroll
        for (int r = 0; r < 2; r++) {
            int ef = tid + r*256;
            int h = ef >> 6, e = ef & 63;
            const float* kb = kptv_s + h*MF*ES;
            const float* qb = qp_s + h*MF;
            float sum = 0.f;
            #pragma unroll
            for (int mm = 0; mm < MF; mm++) sum += qb[mm] * kb[mm*ES + e];
            g_y[tok*EMBD + ef] = __float2half_rn(sum * invD[h]);
        }
        __syncthreads();
    }
}

// =====================================================================
// fp16 tensor-core GEMM via mma.sync.m16n8k16 (f32 accumulate)
// C[m,n] = sum_k A[m,k]*B[n,k] + bias[n] (+gelu)(+res)
// 128x128 tile, 8 warps (2M x 4N, warp 64x32), K-chunk 32 halves,
// cp.async 2-stage pipeline, padded K-contiguous half tiles.
// =====================================================================
#define GT_M 128
#define GT_N 128
#define GK   32
#define TPADH 40                               /* halves per row in smem */
#define STAGE_HALF (2 * 128 * TPADH)           /* A tile + B tile halves */
#define GEMM_SMEM  (2 * STAGE_HALF * 2)        /* 40960 B */

__device__ __forceinline__ uint32_t smem_u32(const void* p) {
    uint32_t a;
    asm("{ .reg .u64 t; cvta.to.shared.u64 t, %1; cvt.u32.u64 %0, t; }"
        : "=r"(a) : "l"(p));
    return a;
}
__device__ __forceinline__ void cp16(uint32_t s, const void* g) {
    asm volatile("cp.async.cg.shared.global [%0], [%1], 16;" :: "r"(s), "l"(g));
}
__device__ __forceinline__ void cp_commit() { asm volatile("cp.async.commit_group;"); }
template<int N> __device__ __forceinline__ void cp_wait() {
    asm volatile("cp.async.wait_group %0;" :: "n"(N));
}
__device__ __forceinline__ void mma16816(float* c, const uint32_t* a, const uint32_t* b) {
    asm volatile("mma.sync.aligned.m16n8k16.row.col.f32.f16.f16.f32 "
        "{%0,%1,%2,%3}, {%4,%5,%6,%7}, {%8,%9}, {%0,%1,%2,%3};"
        : "+f"(c[0]), "+f"(c[1]), "+f"(c[2]), "+f"(c[3])
        : "r"(a[0]), "r"(a[1]), "r"(a[2]), "r"(a[3]), "r"(b[0]), "r"(b[1]));
}

template<bool GELU, bool RES, bool OUTH>
__global__ __launch_bounds__(256) void tc_gemm(
    const __half* __restrict__ A,   // [M,K]
    const __half* __restrict__ B,   // [N,K]
    const float* __restrict__ bias, // [N]
    const float* __restrict__ res,  // [M,N] or nullptr
    void* __restrict__ Cv,          // [M,N] float or half
    int N, int K)
{
    extern __shared__ __align__(16) __half smh[];
    uint32_t sb = smem_u32(smh);
    int tid  = threadIdx.x;
    int warp = tid >> 5, lane = tid & 31;
    int gid  = lane >> 2, tig = lane & 3;
    int m0 = blockIdx.y * GT_M;
    int n0 = blockIdx.x * GT_N;
    int mw = (warp >> 2) * 64;       // warp M offset
    int nw = (warp & 3) * 32;        // warp N offset

    // cp.async: thread -> row = tid>>1, 32B half-segment = (tid&1)*32
    int lrow = tid >> 1;
    int lofs = (tid & 1) * 32;       // bytes within 64B row-chunk
    const char* gA = (const char*)(A + (size_t)(m0 + lrow) * K) + lofs;
    const char* gB = (const char*)(B + (size_t)(n0 + lrow) * K) + lofs;
    uint32_t sA = sb + lrow * (TPADH*2) + lofs;
    uint32_t sB = sA + 128 * (TPADH*2);

    float acc[4][4][4];
    #pragma unroll
    for (int i = 0; i < 4; i++)
        #pragma unroll
        for (int j = 0; j < 4; j++)
            #pragma unroll
            for (int r = 0; r < 4; r++) acc[i][j][r] = 0.f;

    const int NC = K / GK;

    auto load_chunk = [&](int kc, int s) {
        uint32_t so = s * STAGE_HALF * 2;
        size_t go = (size_t)kc * (GK * 2);
        cp16(sA + so,      gA + go);
        cp16(sA + so + 16, gA + go + 16);
        cp16(sB + so,      gB + go);
        cp16(sB + so + 16, gB + go + 16);
        cp_commit();
    };

    load_chunk(0, 0);

    for (int c = 0; c < NC; c++) {
        int s = c & 1;
        if (c + 1 < NC) { load_chunk(c + 1, s ^ 1); cp_wait<1>(); }
        else            { cp_wait<0>(); }
        __syncthreads();

        const __half* As = smh + s * STAGE_HALF;
        const __half* Bs = As + 128 * TPADH;

        #pragma unroll
        for (int kk = 0; kk < GK; kk += 16) {
            uint32_t a[4][4], b[4][2];
            #pragma unroll
            for (int mt = 0; mt < 4; mt++) {
                int r = mw + mt * 16 + gid;
                a[mt][0] = *(const uint32_t*)(As + r * TPADH + kk + 2*tig);
                a[mt][1] = *(const uint32_t*)(As + (r + 8) * TPADH + kk + 2*tig);
                a[mt][2] = *(const uint32_t*)(As + r * TPADH + kk + 2*tig + 8);
                a[mt][3] = *(const uint32_t*)(As + (r + 8) * TPADH + kk + 2*tig + 8);
            }
            #pragma unroll
            for (int nt = 0; nt < 4; nt++) {
                int rn = nw + nt * 8 + gid;
                b[nt][0] = *(const uint32_t*)(Bs + rn * TPADH + kk + 2*tig);
                b[nt][1] = *(const uint32_t*)(Bs + rn * TPADH + kk + 2*tig + 8);
            }
            #pragma unroll
            for (int mt = 0; mt < 4; mt++)
                #pragma unroll
                for (int nt = 0; nt < 4; nt++)
                    mma16816(acc[mt][nt], a[mt], b[nt]);
        }
        __syncthreads();
    }

    // ---- epilogue ----
    #pragma unroll
    for (int mt = 0; mt < 4; mt++) {
        #pragma unroll
        for (int half = 0; half < 2; half++) {
            size_t row = (size_t)(m0 + mw + mt * 16 + gid + half * 8);
            #pragma unroll
            for (int nt = 0; nt < 4; nt++) {
                int col = n0 + nw + nt * 8 + tig * 2;
                float vx = acc[mt][nt][half * 2 + 0] + bias[col];
                float vy = acc[mt][nt][half * 2 + 1] + bias[col + 1];
                if (GELU) {
                    vx = 0.5f * vx * (1.0f + erff(vx * 0.70710678118654752f));
                    vy = 0.5f * vy * (1.0f + erff(vy * 0.70710678118654752f));
                }
                if (RES) {
                    float2 rv = *(const float2*)(res + row * N + col);
                    vx += rv.x; vy += rv.y;
                }
                if (OUTH) {
                    __half2 h; h.x = __float2half_rn(vx); h.y = __float2half_rn(vy);
                    *(__half2*)((__half*)Cv + row * N + col) = h;
                } else {
                    float2 o; o.x = vx; o.y = vy;
                    *(float2*)((float*)Cv + row * N + col) = o;
                }
            }
        }
    }
}

// ---------------- launch ----------------
extern "C" void kernel_launch(void* const* d_in, const int* in_sizes, int n_in,
                              void* d_out, int out_size)
{
    const float* x      = (const float*)d_in[0];
    const float* w      = (const float*)d_in[1];
    const float* kqv_w  = (const float*)d_in[2];
    const float* kqv_b  = (const float*)d_in[3];
    const float* proj_w = (const float*)d_in[4];
    const float* proj_b = (const float*)d_in[5];
    const float* ln1_g  = (const float*)d_in[6];
    const float* ln1_b  = (const float*)d_in[7];
    const float* ln2_g  = (const float*)d_in[8];
    const float* ln2_b  = (const float*)d_in[9];
    const float* mlp_w1 = (const float*)d_in[10];
    const float* mlp_b1 = (const float*)d_in[11];
    const float* mlp_w2 = (const float*)d_in[12];
    const float* mlp_b2 = (const float*)d_in[13];
    float* out = (float*)d_out;

    void *ph1, *pkqv, *pbkqv, *pwkqv, *py, *px1, *ph2, *phid, *pwp, *pw1, *pw2;
    cudaGetSymbolAddress(&ph1,  g_h1);
    cudaGetSymbolAddress(&pkqv, g_kqv);
    cudaGetSymbolAddress(&pbkqv, g_bkqv);
    cudaGetSymbolAddress(&pwkqv, g_wkqv);
    cudaGetSymbolAddress(&py,  g_y);
    cudaGetSymbolAddress(&px1, g_x1);
    cudaGetSymbolAddress(&ph2, g_h2);
    cudaGetSymbolAddress(&phid, g_hid);
    cudaGetSymbolAddress(&pwp, g_wp);
    cudaGetSymbolAddress(&pw1, g_w1);
    cudaGetSymbolAddress(&pw2, g_w2);

    cudaFuncSetAttribute(k3_y, cudaFuncAttributeMaxDynamicSharedMemorySize, K3_SMEM);
    cudaFuncSetAttribute(tc_gemm<false, false, false>, cudaFuncAttributeMaxDynamicSharedMemorySize, GEMM_SMEM);
    cudaFuncSetAttribute(tc_gemm<false, true,  false>, cudaFuncAttributeMaxDynamicSharedMemorySize, GEMM_SMEM);
    cudaFuncSetAttribute(tc_gemm<true,  false, true >, cudaFuncAttributeMaxDynamicSharedMemorySize, GEMM_SMEM);

    // weight prep (half)
    k_round_h<<<(EMBD*EMBD + 255)/256, 256>>>(proj_w, (__half*)pwp, EMBD*EMBD);
    k_round_h<<<(HID*EMBD + 255)/256, 256>>>(mlp_w1, (__half*)pw1, HID*EMBD);
    k_round_h<<<(EMBD*HID + 255)/256, 256>>>(mlp_w2, (__half*)pw2, EMBD*HID);
    k_prep_kqv<<<(256*ES + 255)/256, 256>>>(kqv_w, kqv_b);

    // LN1 -> h1 (half)
    k_ln1<<<BT, 256>>>(x, ln1_g, ln1_b);

    // kqv GEMM: [ROWS,64] @ [256,64]^T -> g_kqv fp32 [ROWS,256]
    tc_gemm<false, false, false><<<dim3(256/GT_N, ROWS/GT_M), 256, GEMM_SMEM>>>(
        (const __half*)ph1, (const __half*)pwkqv, (const float*)pbkqv,
        nullptr, pkqv, 256, ES);

    // features
    k_feat<<<ROWS/32, 256>>>(w);

    // linear attention reductions
    k_zero<<<(BQ*NH*MF*ES + 255)/256, 256>>>();
    k2_kptv<<<dim3(BQ*NH, K2_CH), 256>>>();
    k3_y<<<dim3(TQ/K3_TOK, BQ), 256, K3_SMEM>>>();

    // proj GEMM + residual -> x1 (fp32)
    tc_gemm<false, true, false><<<dim3(EMBD/GT_N, BT/GT_M), 256, GEMM_SMEM>>>(
        (const __half*)py, (const __half*)pwp, proj_b, x, px1, EMBD, EMBD);

    // LN2 -> h2 (half)
    k_ln2<<<BT, 256>>>(ln2_g, ln2_b);

    // MLP1 + gelu -> hid (half)
    tc_gemm<true, false, true><<<dim3(HID/GT_N, BT/GT_M), 256, GEMM_SMEM>>>(
        (const __half*)ph2, (const __half*)pw1, mlp_b1, nullptr, phid, HID, EMBD);

    // MLP2 + residual -> out (fp32)
    tc_gemm<false, true, false><<<dim3(EMBD/GT_N, BT/GT_M), 256, GEMM_SMEM>>>(
        (const __half*)phid, (const __half*)pw2, mlp_b2, (const float*)px1, out, EMBD, HID);
}